// round 11
// baseline (speedup 1.0000x reference)
#include <cuda_runtime.h>
#include <cuda_bf16.h>
#include <math.h>

#define NB 8
#define NS 19
using u64 = unsigned long long;
using u32 = unsigned int;

__device__ float g_y1[(size_t)NB*32*256*256];
__device__ float g_y2[(size_t)NB*64*128*128];
__device__ float g_y3[(size_t)NB*128*64*64];
__device__ float g_y4[(size_t)NB*256*128*128];
__device__ float g_mean1[NB*32],  g_inv1[NB*32];
__device__ float g_mean2[NB*64],  g_inv2[NB*64];
__device__ float g_mean3[NB*128], g_inv3[NB*128];
__device__ float g_mean4[NB*256], g_inv4[NB*256];
__device__ float g_s1[NB*32],  g_q1[NB*32];
__device__ float g_s2[NB*64],  g_q2[NB*64];
__device__ float g_s3[NB*128], g_q3[NB*128];
__device__ float g_s4[NB*256], g_q4[NB*256];
__device__ int   g_label[NB*128*128];
__device__ float g_counts[NB*NS];
__device__ float g_sums[(size_t)NB*NS*512];
__device__ __nv_bfloat16 g_xh[(size_t)NB*128*128*256];  // NHWC norm+lrelu hi
__device__ __nv_bfloat16 g_xl[(size_t)NB*128*128*256];  // lo
__device__ __nv_bfloat16 g_wh[9*8*512*32];              // [tap*8+ch][co][ci32] hi
__device__ __nv_bfloat16 g_wl[9*8*512*32];              // lo

__device__ __forceinline__ u64 pk2(float v){u64 r;asm("mov.b64 %0,{%1,%1};":"=l"(r):"f"(v));return r;}
__device__ __forceinline__ u64 pk2(float a,float b){u64 r;asm("mov.b64 %0,{%1,%2};":"=l"(r):"f"(a),"f"(b));return r;}
__device__ __forceinline__ void fma2(u64&a,u64 v,u64 w){asm("fma.rn.f32x2 %0,%1,%2,%0;":"+l"(a):"l"(v),"l"(w));}
__device__ __forceinline__ float2 upk(u64 a){float2 f;asm("mov.b64 {%0,%1},%2;":"=f"(f.x),"=f"(f.y):"l"(a));return f;}
__device__ __forceinline__ float nl(float x,float m,float iv){float t=(x-m)*iv;return t>0.f?t:0.2f*t;}
__device__ __forceinline__ float tanh_fast(float x){float r;asm("tanh.approx.f32 %0,%1;":"=f"(r):"f"(x));return r;}
__device__ __forceinline__ u32 smem_u32(const void*p){u32 a;asm("{ .reg .u64 t; cvta.to.shared.u64 t,%1; cvt.u32.u64 %0,t; }":"=r"(a):"l"(p));return a;}

// warp all-reduce (sum) of one float
__device__ __forceinline__ float wred(float v){
#pragma unroll
    for(int o=16;o>0;o>>=1)v+=__shfl_xor_sync(~0u,v,o);
    return v;
}

// row-pair packed swizzled tile offset: tile = 128 rows x 32 bf16 (64B rows, pairs share 128B)
__device__ __forceinline__ u32 toff(int row,int colb){
    u32 o=((u32)(row>>1)<<7)+((u32)(row&1)<<6)+(u32)colb;
    return o^((o>>3)&0x70);
}
#define LDSM4(r,addr) asm volatile("ldmatrix.sync.aligned.m8n8.x4.shared.b16 {%0,%1,%2,%3},[%4];" \
    :"=r"((r)[0]),"=r"((r)[1]),"=r"((r)[2]),"=r"((r)[3]):"r"(addr))
#define MMA(d,a,b0,b1) asm volatile("mma.sync.aligned.m16n8k16.row.col.f32.bf16.bf16.f32 " \
    "{%0,%1,%2,%3},{%4,%5,%6,%7},{%8,%9},{%0,%1,%2,%3};" \
    :"+f"((d)[0]),"+f"((d)[1]),"+f"((d)[2]),"+f"((d)[3]) \
    :"r"((a)[0]),"r"((a)[1]),"r"((a)[2]),"r"((a)[3]),"r"(b0),"r"(b1))
#define CPA(dst,src) asm volatile("cp.async.ca.shared.global [%0],[%1],16;"::"r"(dst),"l"(src):"memory")
#define CPA_COMMIT() asm volatile("cp.async.commit_group;":::"memory")

// ---- zero stat accumulators ----
__global__ void __launch_bounds__(256) zero_stats_kernel(){
    const int i=blockIdx.x*256+threadIdx.x;
    if(i<NB*256){g_s4[i]=0.f;g_q4[i]=0.f;}
    if(i<NB*128){g_s3[i]=0.f;g_q3[i]=0.f;}
    if(i<NB*64){g_s2[i]=0.f;g_q2[i]=0.f;}
    if(i<NB*32){g_s1[i]=0.f;g_q1[i]=0.f;}
}

// ---- stat finalize: (sum,sumsq) -> (mean, rsqrt) ----
__device__ __forceinline__ void fin_body(const float* s,const float* q,float* mean,float* inv,int n,float rHW){
    const int i=blockIdx.x*256+threadIdx.x;
    if(i>=n)return;
    const float m=s[i]*rHW;
    mean[i]=m;
    inv[i]=rsqrtf(q[i]*rHW-m*m+1e-5f);
}
__global__ void __launch_bounds__(256) fin1_kernel(){fin_body(g_s1,g_q1,g_mean1,g_inv1,NB*32,1.f/65536.f);}
__global__ void __launch_bounds__(256) fin2_kernel(){fin_body(g_s2,g_q2,g_mean2,g_inv2,NB*64,1.f/16384.f);}
__global__ void __launch_bounds__(256) fin3_kernel(){fin_body(g_s3,g_q3,g_mean3,g_inv3,NB*128,1.f/4096.f);}
__global__ void __launch_bounds__(256) fin4_kernel(){fin_body(g_s4,g_q4,g_mean4,g_inv4,NB*256,1.f/16384.f);}

// ---- conv1: 3->32, reflect, 256x256, fused stats ----
__global__ void __launch_bounds__(256) conv1_kernel(const float* __restrict__ x,const float* __restrict__ w){
    __shared__ float s_in[3][18][18];
    __shared__ u64 s_w[27][16];
    __shared__ float rs[32],rq[32];
    const int tx=threadIdx.x,ty=threadIdx.y,tid=ty*16+tx;
    const int ox0=blockIdx.x*16,oy0=blockIdx.y*16,b=blockIdx.z;
    if(tid<32){rs[tid]=0.f;rq[tid]=0.f;}
    for(int e=tid;e<27*16;e+=256){int j=e&15,r=e>>4;s_w[r][j]=pk2(w[(2*j)*27+r],w[(2*j+1)*27+r]);}
    for(int e=tid;e<3*18*18;e+=256){
        int c=e/324,r=e%324,yy=r/18,xx=r%18;
        int iy=oy0-1+yy;iy=iy<0?-iy:(iy>255?510-iy:iy);
        int ix=ox0-1+xx;ix=ix<0?-ix:(ix>255?510-ix:ix);
        s_in[c][yy][xx]=x[(((size_t)b*3+c)*256+iy)*256+ix];
    }
    __syncthreads();
    u64 acc[16];
#pragma unroll
    for(int j=0;j<16;++j)acc[j]=0ull;
#pragma unroll
    for(int c=0;c<3;++c)
#pragma unroll
        for(int k=0;k<9;++k){
            u64 vv=pk2(s_in[c][ty+k/3][tx+k%3]);
#pragma unroll
            for(int j=0;j<16;++j)fma2(acc[j],vv,s_w[c*9+k][j]);
        }
    float* yp=g_y1+(size_t)b*32*65536+(size_t)(oy0+ty)*256+ox0+tx;
#pragma unroll
    for(int j=0;j<16;++j){
        float2 v=upk(acc[j]);
        yp[(size_t)(2*j)*65536]=v.x;yp[(size_t)(2*j+1)*65536]=v.y;
        float s0=wred(v.x),q0=wred(v.x*v.x),s1=wred(v.y),q1=wred(v.y*v.y);
        if((tid&31)==0){atomicAdd(&rs[2*j],s0);atomicAdd(&rq[2*j],q0);atomicAdd(&rs[2*j+1],s1);atomicAdd(&rq[2*j+1],q1);}
    }
    __syncthreads();
    if(tid<32){atomicAdd(&g_s1[b*32+tid],rs[tid]);atomicAdd(&g_q1[b*32+tid],rq[tid]);}
}

// ---- stride-2 conv, fused stats ----
template<int CIN,int COUT,int HIN>
__device__ __forceinline__ void conv_s2_body(const float* __restrict__ x,const float* mean,const float* inv,
                                             const float* __restrict__ w,float* __restrict__ y,
                                             float* gs,float* gq){
    constexpr int HOUT=HIN/2,CK=4,TILESX=HOUT/32;
    __shared__ float s_in[CK][33][65];
    __shared__ u64 s_w[CK*9][16];
    __shared__ float rs[32],rq[32];
    const int tx=threadIdx.x,ty=threadIdx.y,tid=ty*16+tx;
    const int co0=blockIdx.x*32;
    const int oy0=(blockIdx.y/TILESX)*16,ox0=(blockIdx.y%TILESX)*32,b=blockIdx.z;
    if(tid<32){rs[tid]=0.f;rq[tid]=0.f;}
    u64 a0[16],a1[16];
#pragma unroll
    for(int j=0;j<16;++j){a0[j]=0ull;a1[j]=0ull;}
    for(int c0=0;c0<CIN;c0+=CK){
        __syncthreads();
        for(int e=tid;e<CK*9*16;e+=256){
            int j=e&15,r=e>>4,c=r/9,k=r%9;
            size_t base=((size_t)(co0+2*j)*CIN+c0+c)*9+k;
            s_w[r][j]=pk2(w[base],w[base+(size_t)CIN*9]);
        }
        for(int e=tid;e<CK*33*65;e+=256){
            int c=e/(33*65),r=e%(33*65),yy=r/65,xx=r%65;
            int iy=2*oy0-1+yy,ix=2*ox0-1+xx;float v=0.f;
            if(iy>=0&&iy<HIN&&ix>=0&&ix<HIN){int ch=b*CIN+c0+c;v=nl(x[((size_t)ch*HIN+iy)*HIN+ix],mean[ch],inv[ch]);}
            s_in[c][yy][xx]=v;
        }
        __syncthreads();
#pragma unroll
        for(int c=0;c<CK;++c)
#pragma unroll
            for(int k=0;k<9;++k){
                const int ky=k/3,kx=k%3;
                u64 v0=pk2(s_in[c][2*ty+ky][2*tx+kx]);
                u64 v1=pk2(s_in[c][2*ty+ky][2*(tx+16)+kx]);
#pragma unroll
                for(int j=0;j<16;++j){u64 wv=s_w[c*9+k][j];fma2(a0[j],v0,wv);fma2(a1[j],v1,wv);}
            }
    }
#pragma unroll
    for(int j=0;j<16;++j){
        float2 p0=upk(a0[j]),p1=upk(a1[j]);
        size_t base=((size_t)(b*COUT+co0+2*j)*HOUT+oy0+ty)*HOUT+ox0+tx;
        y[base]=p0.x;y[base+(size_t)HOUT*HOUT]=p0.y;y[base+16]=p1.x;y[base+(size_t)HOUT*HOUT+16]=p1.y;
        float s0=wred(p0.x+p1.x),q0=wred(p0.x*p0.x+p1.x*p1.x);
        float s1=wred(p0.y+p1.y),q1=wred(p0.y*p0.y+p1.y*p1.y);
        if((tid&31)==0){atomicAdd(&rs[2*j],s0);atomicAdd(&rq[2*j],q0);atomicAdd(&rs[2*j+1],s1);atomicAdd(&rq[2*j+1],q1);}
    }
    __syncthreads();
    if(tid<32){atomicAdd(&gs[b*COUT+co0+tid],rs[tid]);atomicAdd(&gq[b*COUT+co0+tid],rq[tid]);}
}
__global__ void __launch_bounds__(256) conv2_kernel(const float* __restrict__ w){conv_s2_body<32,64,256>(g_y1,g_mean1,g_inv1,w,g_y2,g_s2,g_q2);}
__global__ void __launch_bounds__(256) conv3_kernel(const float* __restrict__ w){conv_s2_body<64,128,128>(g_y2,g_mean2,g_inv2,w,g_y3,g_s3,g_q3);}

// ---- convT4 subpixel, fused stats ----
__global__ void __launch_bounds__(256) conv4_kernel(const float* __restrict__ w){
    constexpr int CK=8;
    __shared__ float s_in[CK][17][33];
    __shared__ u64 s_w[CK*9][4];
    __shared__ float rs[8],rq[8];
    const int tx=threadIdx.x,ty=threadIdx.y,tid=ty*16+tx;
    const int co0=blockIdx.x*8,qy0=(blockIdx.y>>1)*16,qx0=(blockIdx.y&1)*32,b=blockIdx.z;
    if(tid<8){rs[tid]=0.f;rq[tid]=0.f;}
    u64 acc[2][4][4];
#pragma unroll
    for(int q=0;q<2;++q)
#pragma unroll
        for(int o=0;o<4;++o)
#pragma unroll
            for(int j=0;j<4;++j)acc[q][o][j]=0ull;
    for(int c0=0;c0<128;c0+=CK){
        __syncthreads();
        for(int e=tid;e<CK*9*4;e+=256){
            int j=e&3,r=e>>2,c=r/9,k=r%9;
            size_t base=((size_t)(c0+c)*256+co0+2*j)*9+k;
            s_w[r][j]=pk2(w[base],w[base+9]);
        }
        for(int e=tid;e<CK*17*33;e+=256){
            int c=e/(17*33),r=e%(17*33),yy=r/33,xx=r%33;
            int iy=qy0+yy,ix=qx0+xx;float v=0.f;
            if(iy<64&&ix<64){int ch=b*128+c0+c;v=nl(g_y3[((size_t)ch*64+iy)*64+ix],g_mean3[ch],g_inv3[ch]);}
            s_in[c][yy][xx]=v;
        }
        __syncthreads();
#pragma unroll
        for(int c=0;c<CK;++c)
#pragma unroll
            for(int q=0;q<2;++q){
                const int qx=tx+q*16;
                u64 i00=pk2(s_in[c][ty][qx]),i01=pk2(s_in[c][ty][qx+1]);
                u64 i10=pk2(s_in[c][ty+1][qx]),i11=pk2(s_in[c][ty+1][qx+1]);
#pragma unroll
                for(int j=0;j<4;++j){
                    fma2(acc[q][0][j],i00,s_w[c*9+4][j]);
                    fma2(acc[q][1][j],i01,s_w[c*9+3][j]);fma2(acc[q][1][j],i00,s_w[c*9+5][j]);
                    fma2(acc[q][2][j],i10,s_w[c*9+1][j]);fma2(acc[q][2][j],i00,s_w[c*9+7][j]);
                    fma2(acc[q][3][j],i11,s_w[c*9+0][j]);fma2(acc[q][3][j],i10,s_w[c*9+2][j]);
                    fma2(acc[q][3][j],i01,s_w[c*9+6][j]);fma2(acc[q][3][j],i00,s_w[c*9+8][j]);
                }
            }
    }
#pragma unroll
    for(int q=0;q<2;++q){
        const int Y=qy0+ty,X=qx0+tx+q*16;
#pragma unroll
        for(int j=0;j<4;++j){
            float* yp=g_y4+((size_t)(b*256+co0+2*j)*128+2*Y)*128+2*X;
            float2 vee=upk(acc[q][0][j]),veo=upk(acc[q][1][j]),voe=upk(acc[q][2][j]),voo=upk(acc[q][3][j]);
            yp[0]=vee.x;yp[1]=veo.x;yp[128]=voe.x;yp[129]=voo.x;
            yp[16384]=vee.y;yp[16385]=veo.y;yp[16384+128]=voe.y;yp[16384+129]=voo.y;
        }
    }
#pragma unroll
    for(int j=0;j<4;++j){
        float s0=0.f,sq0=0.f,s1=0.f,sq1=0.f;
#pragma unroll
        for(int q=0;q<2;++q)
#pragma unroll
            for(int o=0;o<4;++o){
                float2 v=upk(acc[q][o][j]);
                s0+=v.x;sq0+=v.x*v.x;s1+=v.y;sq1+=v.y*v.y;
            }
        s0=wred(s0);sq0=wred(sq0);s1=wred(s1);sq1=wred(sq1);
        if((tid&31)==0){atomicAdd(&rs[2*j],s0);atomicAdd(&rq[2*j],sq0);atomicAdd(&rs[2*j+1],s1);atomicAdd(&rq[2*j+1],sq1);}
    }
    __syncthreads();
    if(tid<8){atomicAdd(&g_s4[b*256+co0+tid],rs[tid]);atomicAdd(&g_q4[b*256+co0+tid],rq[tid]);}
}

// ---- conv5 prep ----
__global__ void __launch_bounds__(256) prep_w_kernel(const float* __restrict__ w5){
    const int idx=blockIdx.x*256+threadIdx.x;
    if(idx>=512*2304)return;
    const int co=idx/2304,r=idx%2304,ci=r/9,k=r%9;
    float v=w5[idx];
    __nv_bfloat16 hi=__float2bfloat16(v);
    __nv_bfloat16 lo=__float2bfloat16(v-__bfloat162float(hi));
    const int dst=((k*8+(ci>>5))*512+co)*32+(ci&31);
    g_wh[dst]=hi;g_wl[dst]=lo;
}
__global__ void __launch_bounds__(256) prep_x_kernel(){
    __shared__ float tile[32][129];
    const int y=blockIdx.x,b=blockIdx.y,tid=threadIdx.x;
    u32* oh=reinterpret_cast<u32*>(g_xh)+((size_t)(b*128+y)*128)*128;
    u32* ol=reinterpret_cast<u32*>(g_xl)+((size_t)(b*128+y)*128)*128;
    for(int c0=0;c0<256;c0+=32){
        for(int e=tid;e<32*128;e+=256){
            const int cl=e>>7,x=e&127,ch=b*256+c0+cl;
            tile[cl][x]=nl(g_y4[((size_t)ch*128+y)*128+x],g_mean4[ch],g_inv4[ch]);
        }
        __syncthreads();
        for(int e=tid;e<128*16;e+=256){
            const int x=e>>4,cp=e&15;
            float v0=tile[2*cp][x],v1=tile[2*cp+1][x];
            __nv_bfloat16 h0=__float2bfloat16(v0),h1=__float2bfloat16(v1);
            __nv_bfloat16 l0=__float2bfloat16(v0-__bfloat162float(h0)),l1=__float2bfloat16(v1-__bfloat162float(h1));
            __nv_bfloat162 hh;hh.x=h0;hh.y=h1;
            __nv_bfloat162 ll;ll.x=l0;ll.y=l1;
            oh[(size_t)x*128+(c0>>1)+cp]=*reinterpret_cast<u32*>(&hh);
            ol[(size_t)x*128+(c0>>1)+cp]=*reinterpret_cast<u32*>(&ll);
        }
        __syncthreads();
    }
}

// ---- conv5: HMMA implicit GEMM + cp.async double-buffer + fused region pooling ----
static constexpr int C5_BINS = 65536;
static constexpr int C5_SLAB = C5_BINS + NS*128*4;
static constexpr int C5_SMEM = C5_SLAB + 512;
__global__ void __launch_bounds__(256) conv5_hmma_kernel(const float* __restrict__ bias){
    extern __shared__ __align__(128) char dsm[];
    const u32 sb=smem_u32(dsm);
    float* bins=reinterpret_cast<float*>(dsm+C5_BINS);
    int* slab=reinterpret_cast<int*>(dsm+C5_SLAB);
    const int tid=threadIdx.x,w=tid>>5,lane=tid&31;
    const int co0=blockIdx.x*128,y=blockIdx.y,b=blockIdx.z;
    const int wm=w&3,wn=w>>2;
    const int i8=lane&7,q=lane>>3;

    for(int i=tid;i<NS*128;i+=256)bins[i]=0.f;
    if(tid<128)slab[tid]=g_label[b*16384+y*128+tid];

    float acc[2][8][4];
#pragma unroll
    for(int mi=0;mi<2;++mi)
#pragma unroll
        for(int n8=0;n8<8;++n8)
#pragma unroll
            for(int j=0;j<4;++j)acc[mi][n8][j]=0.f;

    const int rA0=wm*32+i8+((q&1)<<3), rA1=rA0+16;
    const int rB0=wn*64+i8+((q>>1)<<3), rB1=rB0+16, rB2=rB0+32, rB3=rB0+48;
    const int cAq=(q>>1)<<4, cBq=(q&1)<<4;

    const int er=tid>>2, ec8=tid&3;
    const u32 sto=toff(er,ec8*16), sto2=toff(er+64,ec8*16);

    auto stage=[&](int r,u32 sbase){
        const int tap=r>>3,ch=r&7;
        const int ky=tap/3,kx=tap%3;
        int ys=y+ky-1; ys=ys<0?1:(ys>127?126:ys);
        int xs=er+kx-1; xs=xs<0?1:(xs>127?126:xs);
        const int er2=er+64;
        int xs2=er2+kx-1; xs2=xs2>127?126:xs2;
        const size_t a0=((size_t)(r*512+co0)+er)*32+ec8*8;
        const size_t a1=a0+(size_t)64*32;
        const size_t b0o=((size_t)(b*128+ys)*128+xs)*256+ch*32+ec8*8;
        const size_t b1o=((size_t)(b*128+ys)*128+xs2)*256+ch*32+ec8*8;
        const u32 d0=sbase+sto,d1=sbase+sto2;
        CPA(d0      ,g_wh+a0); CPA(d0+8192 ,g_wl+a0);
        CPA(d0+16384,g_xh+b0o);CPA(d0+24576,g_xl+b0o);
        CPA(d1      ,g_wh+a1); CPA(d1+8192 ,g_wl+a1);
        CPA(d1+16384,g_xh+b1o);CPA(d1+24576,g_xl+b1o);
        CPA_COMMIT();
    };

    stage(0,sb);
    for(int r=0;r<72;++r){
        const u32 cur=sb+(u32)((r&1)<<15);
        if(r<71){
            stage(r+1,sb+(u32)(((r+1)&1)<<15));
            asm volatile("cp.async.wait_group 1;":::"memory");
        }else{
            asm volatile("cp.async.wait_group 0;":::"memory");
        }
        __syncthreads();
        const u32 uAh=cur,uAl=cur+8192,uBh=cur+16384,uBl=cur+24576;
#pragma unroll
        for(int ks=0;ks<2;++ks){
            const int k0b=ks*32;
            u32 Ah0[4],Ah1[4],Al0[4],Al1[4];
            LDSM4(Ah0,uAh+toff(rA0,k0b+cAq));
            LDSM4(Ah1,uAh+toff(rA1,k0b+cAq));
            LDSM4(Al0,uAl+toff(rA0,k0b+cAq));
            LDSM4(Al1,uAl+toff(rA1,k0b+cAq));
            const int rB[4]={rB0,rB1,rB2,rB3};
#pragma unroll
            for(int nb=0;nb<4;++nb){
                u32 Bh[4],Bl[4];
                LDSM4(Bh,uBh+toff(rB[nb],k0b+cBq));
                LDSM4(Bl,uBl+toff(rB[nb],k0b+cBq));
                MMA(acc[0][nb*2  ],Ah0,Bh[0],Bh[1]);
                MMA(acc[0][nb*2+1],Ah0,Bh[2],Bh[3]);
                MMA(acc[1][nb*2  ],Ah1,Bh[0],Bh[1]);
                MMA(acc[1][nb*2+1],Ah1,Bh[2],Bh[3]);
                MMA(acc[0][nb*2  ],Ah0,Bl[0],Bl[1]);
                MMA(acc[0][nb*2+1],Ah0,Bl[2],Bl[3]);
                MMA(acc[1][nb*2  ],Ah1,Bl[0],Bl[1]);
                MMA(acc[1][nb*2+1],Ah1,Bl[2],Bl[3]);
                MMA(acc[0][nb*2  ],Al0,Bh[0],Bh[1]);
                MMA(acc[0][nb*2+1],Al0,Bh[2],Bh[3]);
                MMA(acc[1][nb*2  ],Al1,Bh[0],Bh[1]);
                MMA(acc[1][nb*2+1],Al1,Bh[2],Bh[3]);
            }
        }
        __syncthreads();
    }

    // fused epilogue: bias + tanh + per-label smem bins
    const int g4=lane>>2,tg=lane&3;
#pragma unroll
    for(int mi=0;mi<2;++mi){
        const int cr=wm*32+mi*16+g4;
        const float b0v=bias[co0+cr],b1v=bias[co0+cr+8];
#pragma unroll
        for(int n8=0;n8<8;++n8){
            const int x=wn*64+n8*8+tg*2;
            const int l0=slab[x],l1=slab[x+1];
            atomicAdd(&bins[l0*128+cr  ],tanh_fast(acc[mi][n8][0]+b0v));
            atomicAdd(&bins[l1*128+cr  ],tanh_fast(acc[mi][n8][1]+b0v));
            atomicAdd(&bins[l0*128+cr+8],tanh_fast(acc[mi][n8][2]+b1v));
            atomicAdd(&bins[l1*128+cr+8],tanh_fast(acc[mi][n8][3]+b1v));
        }
    }
    __syncthreads();
    for(int i=tid;i<NS*128;i+=256){
        const float v=bins[i];
        if(v!=0.f)atomicAdd(&g_sums[((size_t)b*NS+(i>>7))*512+co0+(i&127)],v);
    }
}

// ---- labels + counts ----
__global__ void __launch_bounds__(256) label_kernel(const float* __restrict__ segmap){
    const int b=blockIdx.x;
    __shared__ int cnt[NS];
    if(threadIdx.x<NS)cnt[threadIdx.x]=0;
    __syncthreads();
    for(int p=threadIdx.x;p<16384;p+=256){
        const int y=p>>7,x=p&127;
        const float* sp=segmap+(size_t)b*NS*65536+(size_t)(2*y)*256+2*x;
        int lab=0;
#pragma unroll
        for(int s=NS-1;s>=0;--s)
            if(sp[(size_t)s*65536]>0.f)lab=s;
        g_label[b*16384+p]=lab;
        atomicAdd(&cnt[lab],1);
    }
    __syncthreads();
    if(threadIdx.x<NS)g_counts[b*NS+threadIdx.x]=(float)cnt[threadIdx.x];
}
__global__ void __launch_bounds__(256) zero_sums_kernel(){
    const int i=blockIdx.x*256+threadIdx.x;
    if(i<NB*NS*512)g_sums[i]=0.f;
}
__global__ void __launch_bounds__(256) finalize_kernel(float* __restrict__ out){
    const int i=blockIdx.x*256+threadIdx.x;
    if(i>=NB*NS*512)return;
    const float cnt=g_counts[i>>9];
    out[i]=cnt>0.f?g_sums[i]/fmaxf(cnt,1.f):0.f;
}

extern "C" void kernel_launch(void* const* d_in, const int* in_sizes, int n_in,
                              void* d_out, int out_size)
{
    const float* input =(const float*)d_in[0];
    const float* segmap=(const float*)d_in[1];
    const float* w1=(const float*)d_in[2];
    const float* w2=(const float*)d_in[4];
    const float* w3=(const float*)d_in[6];
    const float* w4=(const float*)d_in[8];
    const float* w5=(const float*)d_in[10];
    const float* b5=(const float*)d_in[11];
    float* out=(float*)d_out;

    cudaFuncSetAttribute(conv5_hmma_kernel,cudaFuncAttributeMaxDynamicSharedMemorySize,C5_SMEM);

    dim3 t2(16,16);
    zero_stats_kernel<<<8,256>>>();
    conv1_kernel<<<dim3(16,16,NB),t2>>>(input,w1);
    fin1_kernel<<<1,256>>>();
    conv2_kernel<<<dim3(2,32,NB),t2>>>(w2);
    fin2_kernel<<<2,256>>>();
    prep_w_kernel<<<(512*2304+255)/256,256>>>(w5);
    conv3_kernel<<<dim3(4,8,NB),t2>>>(w3);
    fin3_kernel<<<4,256>>>();
    conv4_kernel<<<dim3(32,8,NB),t2>>>(w4);
    fin4_kernel<<<8,256>>>();
    prep_x_kernel<<<dim3(128,NB),256>>>();
    label_kernel<<<NB,256>>>(segmap);
    zero_sums_kernel<<<(NB*NS*512+255)/256,256>>>();
    conv5_hmma_kernel<<<dim3(4,128,NB),256,C5_SMEM>>>(b5);
    finalize_kernel<<<(NB*NS*512+255)/256,256>>>(out);
}

// round 12
// speedup vs baseline: 1.1878x; 1.1878x over previous
#include <cuda_runtime.h>
#include <cuda_bf16.h>
#include <math.h>

#define NB 8
#define NS 19
using u64 = unsigned long long;
using u32 = unsigned int;

__device__ float g_y1[(size_t)NB*32*256*256];
__device__ float g_y2[(size_t)NB*64*128*128];
__device__ float g_y3[(size_t)NB*128*64*64];
__device__ float g_y4[(size_t)NB*256*128*128];
__device__ float g_mean1[NB*32],  g_inv1[NB*32];
__device__ float g_mean2[NB*64],  g_inv2[NB*64];
__device__ float g_mean3[NB*128], g_inv3[NB*128];
__device__ float g_mean4[NB*256], g_inv4[NB*256];
__device__ int   g_label[NB*128*128];
__device__ float g_counts[NB*NS];
__device__ float g_sums[(size_t)NB*NS*512];
__device__ __nv_bfloat16 g_xh[(size_t)NB*128*128*256];  // conv5 input NHWC hi
__device__ __nv_bfloat16 g_xl[(size_t)NB*128*128*256];  // lo
__device__ __nv_bfloat16 g_wh[9*8*512*32];              // conv5 weights [tap*8+ch][co][ci32] hi
__device__ __nv_bfloat16 g_wl[9*8*512*32];              // lo
__device__ __nv_bfloat16 g_x3h[(size_t)NB*64*64*128];   // conv4 input NHWC hi (norm3+lrelu)
__device__ __nv_bfloat16 g_x3l[(size_t)NB*64*64*128];   // lo
__device__ __nv_bfloat16 g_w4h[9*4*256*32];             // conv4 weights [tap*4+ch][co][ci32] hi
__device__ __nv_bfloat16 g_w4l[9*4*256*32];             // lo

__device__ __forceinline__ u64 pk2(float v){u64 r;asm("mov.b64 %0,{%1,%1};":"=l"(r):"f"(v));return r;}
__device__ __forceinline__ u64 pk2(float a,float b){u64 r;asm("mov.b64 %0,{%1,%2};":"=l"(r):"f"(a),"f"(b));return r;}
__device__ __forceinline__ void fma2(u64&a,u64 v,u64 w){asm("fma.rn.f32x2 %0,%1,%2,%0;":"+l"(a):"l"(v),"l"(w));}
__device__ __forceinline__ float2 upk(u64 a){float2 f;asm("mov.b64 {%0,%1},%2;":"=f"(f.x),"=f"(f.y):"l"(a));return f;}
__device__ __forceinline__ float nl(float x,float m,float iv){float t=(x-m)*iv;return t>0.f?t:0.2f*t;}
__device__ __forceinline__ float tanh_fast(float x){float r;asm("tanh.approx.f32 %0,%1;":"=f"(r):"f"(x));return r;}
__device__ __forceinline__ u32 smem_u32(const void*p){u32 a;asm("{ .reg .u64 t; cvta.to.shared.u64 t,%1; cvt.u32.u64 %0,t; }":"=r"(a):"l"(p));return a;}

// row-pair packed swizzled tile offset: rows x 32 bf16 (64B rows, pairs share 128B)
__device__ __forceinline__ u32 toff(int row,int colb){
    u32 o=((u32)(row>>1)<<7)+((u32)(row&1)<<6)+(u32)colb;
    return o^((o>>3)&0x70);
}
#define LDSM4(r,addr) asm volatile("ldmatrix.sync.aligned.m8n8.x4.shared.b16 {%0,%1,%2,%3},[%4];" \
    :"=r"((r)[0]),"=r"((r)[1]),"=r"((r)[2]),"=r"((r)[3]):"r"(addr))
#define MMA(d,a,b0,b1) asm volatile("mma.sync.aligned.m16n8k16.row.col.f32.bf16.bf16.f32 " \
    "{%0,%1,%2,%3},{%4,%5,%6,%7},{%8,%9},{%0,%1,%2,%3};" \
    :"+f"((d)[0]),"+f"((d)[1]),"+f"((d)[2]),"+f"((d)[3]) \
    :"r"((a)[0]),"r"((a)[1]),"r"((a)[2]),"r"((a)[3]),"r"(b0),"r"(b1))
#define CPA(dst,src) asm volatile("cp.async.ca.shared.global [%0],[%1],16;"::"r"(dst),"l"(src):"memory")
#define CPAZ(dst,src,ssz) asm volatile("cp.async.ca.shared.global [%0],[%1],16,%2;"::"r"(dst),"l"(src),"r"(ssz):"memory")
#define CPA_COMMIT() asm volatile("cp.async.commit_group;":::"memory")

// ---- conv1: 3->32, reflect, 256x256 ----
__global__ void __launch_bounds__(256) conv1_kernel(const float* __restrict__ x,const float* __restrict__ w){
    __shared__ float s_in[3][18][18];
    __shared__ u64 s_w[27][16];
    const int tx=threadIdx.x,ty=threadIdx.y,tid=ty*16+tx;
    const int ox0=blockIdx.x*16,oy0=blockIdx.y*16,b=blockIdx.z;
    for(int e=tid;e<27*16;e+=256){int j=e&15,r=e>>4;s_w[r][j]=pk2(w[(2*j)*27+r],w[(2*j+1)*27+r]);}
    for(int e=tid;e<3*18*18;e+=256){
        int c=e/324,r=e%324,yy=r/18,xx=r%18;
        int iy=oy0-1+yy;iy=iy<0?-iy:(iy>255?510-iy:iy);
        int ix=ox0-1+xx;ix=ix<0?-ix:(ix>255?510-ix:ix);
        s_in[c][yy][xx]=x[(((size_t)b*3+c)*256+iy)*256+ix];
    }
    __syncthreads();
    u64 acc[16];
#pragma unroll
    for(int j=0;j<16;++j)acc[j]=0ull;
#pragma unroll
    for(int c=0;c<3;++c)
#pragma unroll
        for(int k=0;k<9;++k){
            u64 vv=pk2(s_in[c][ty+k/3][tx+k%3]);
#pragma unroll
            for(int j=0;j<16;++j)fma2(acc[j],vv,s_w[c*9+k][j]);
        }
    float* yp=g_y1+(size_t)b*32*65536+(size_t)(oy0+ty)*256+ox0+tx;
#pragma unroll
    for(int j=0;j<16;++j){float2 v=upk(acc[j]);yp[(size_t)(2*j)*65536]=v.x;yp[(size_t)(2*j+1)*65536]=v.y;}
}

// ---- IN stats ----
__device__ __forceinline__ void stats_body(const float* __restrict__ y,float* mean,float* inv,int HW){
    const int ch=blockIdx.x;
    const float4* p=reinterpret_cast<const float4*>(y+(size_t)ch*HW);
    float s=0.f,ss=0.f;
    for(int i=threadIdx.x;i<(HW>>2);i+=256){float4 v=p[i];s+=v.x+v.y+v.z+v.w;ss+=v.x*v.x+v.y*v.y+v.z*v.z+v.w*v.w;}
#pragma unroll
    for(int o=16;o>0;o>>=1){s+=__shfl_xor_sync(~0u,s,o);ss+=__shfl_xor_sync(~0u,ss,o);}
    __shared__ float sh[2][8];
    const int wid=threadIdx.x>>5,lid=threadIdx.x&31;
    if(lid==0){sh[0][wid]=s;sh[1][wid]=ss;}
    __syncthreads();
    if(threadIdx.x==0){
        float ts=0.f,tss=0.f;
#pragma unroll
        for(int i=0;i<8;++i){ts+=sh[0][i];tss+=sh[1][i];}
        float m=ts/HW;mean[ch]=m;inv[ch]=rsqrtf(tss/HW-m*m+1e-5f);
    }
}
__global__ void __launch_bounds__(256) stats1_kernel(){stats_body(g_y1,g_mean1,g_inv1,65536);}
__global__ void __launch_bounds__(256) stats2_kernel(){stats_body(g_y2,g_mean2,g_inv2,16384);}
__global__ void __launch_bounds__(256) stats3_kernel(){stats_body(g_y3,g_mean3,g_inv3,4096);}
__global__ void __launch_bounds__(256) stats4_kernel(){stats_body(g_y4,g_mean4,g_inv4,16384);}

// ---- stride-2 conv ----
template<int CIN,int COUT,int HIN>
__device__ __forceinline__ void conv_s2_body(const float* __restrict__ x,const float* mean,const float* inv,
                                             const float* __restrict__ w,float* __restrict__ y){
    constexpr int HOUT=HIN/2,CK=4,TILESX=HOUT/32;
    __shared__ float s_in[CK][33][65];
    __shared__ u64 s_w[CK*9][16];
    const int tx=threadIdx.x,ty=threadIdx.y,tid=ty*16+tx;
    const int co0=blockIdx.x*32;
    const int oy0=(blockIdx.y/TILESX)*16,ox0=(blockIdx.y%TILESX)*32,b=blockIdx.z;
    u64 a0[16],a1[16];
#pragma unroll
    for(int j=0;j<16;++j){a0[j]=0ull;a1[j]=0ull;}
    for(int c0=0;c0<CIN;c0+=CK){
        __syncthreads();
        for(int e=tid;e<CK*9*16;e+=256){
            int j=e&15,r=e>>4,c=r/9,k=r%9;
            size_t base=((size_t)(co0+2*j)*CIN+c0+c)*9+k;
            s_w[r][j]=pk2(w[base],w[base+(size_t)CIN*9]);
        }
        for(int e=tid;e<CK*33*65;e+=256){
            int c=e/(33*65),r=e%(33*65),yy=r/65,xx=r%65;
            int iy=2*oy0-1+yy,ix=2*ox0-1+xx;float v=0.f;
            if(iy>=0&&iy<HIN&&ix>=0&&ix<HIN){int ch=b*CIN+c0+c;v=nl(x[((size_t)ch*HIN+iy)*HIN+ix],mean[ch],inv[ch]);}
            s_in[c][yy][xx]=v;
        }
        __syncthreads();
#pragma unroll
        for(int c=0;c<CK;++c)
#pragma unroll
            for(int k=0;k<9;++k){
                const int ky=k/3,kx=k%3;
                u64 v0=pk2(s_in[c][2*ty+ky][2*tx+kx]);
                u64 v1=pk2(s_in[c][2*ty+ky][2*(tx+16)+kx]);
#pragma unroll
                for(int j=0;j<16;++j){u64 wv=s_w[c*9+k][j];fma2(a0[j],v0,wv);fma2(a1[j],v1,wv);}
            }
    }
#pragma unroll
    for(int j=0;j<16;++j){
        float2 q0=upk(a0[j]),q1=upk(a1[j]);
        size_t base=((size_t)(b*COUT+co0+2*j)*HOUT+oy0+ty)*HOUT+ox0+tx;
        y[base]=q0.x;y[base+(size_t)HOUT*HOUT]=q0.y;y[base+16]=q1.x;y[base+(size_t)HOUT*HOUT+16]=q1.y;
    }
}
__global__ void __launch_bounds__(256) conv2_kernel(const float* __restrict__ w){conv_s2_body<32,64,256>(g_y1,g_mean1,g_inv1,w,g_y2);}
__global__ void __launch_bounds__(256) conv3_kernel(const float* __restrict__ w){conv_s2_body<64,128,128>(g_y2,g_mean2,g_inv2,w,g_y3);}

// ---- conv4 prep: y3 -> NHWC bf16 hi/lo (norm3+lrelu) ----
__global__ void __launch_bounds__(256) prep_x3_kernel(){
    __shared__ float t3[32][65];
    const int y=blockIdx.x,b=blockIdx.y,tid=threadIdx.x;
    u32* oh=reinterpret_cast<u32*>(g_x3h)+((size_t)(b*64+y)*64)*64;
    u32* ol=reinterpret_cast<u32*>(g_x3l)+((size_t)(b*64+y)*64)*64;
    for(int c0=0;c0<128;c0+=32){
        for(int e=tid;e<32*64;e+=256){
            const int cl=e>>6,x=e&63,ch=b*128+c0+cl;
            t3[cl][x]=nl(g_y3[((size_t)ch*64+y)*64+x],g_mean3[ch],g_inv3[ch]);
        }
        __syncthreads();
        for(int e=tid;e<64*16;e+=256){
            const int x=e>>4,cp=e&15;
            float v0=t3[2*cp][x],v1=t3[2*cp+1][x];
            __nv_bfloat16 h0=__float2bfloat16(v0),h1=__float2bfloat16(v1);
            __nv_bfloat16 l0=__float2bfloat16(v0-__bfloat162float(h0)),l1=__float2bfloat16(v1-__bfloat162float(h1));
            __nv_bfloat162 hh;hh.x=h0;hh.y=h1;
            __nv_bfloat162 ll;ll.x=l0;ll.y=l1;
            oh[(size_t)x*64+(c0>>1)+cp]=*reinterpret_cast<u32*>(&hh);
            ol[(size_t)x*64+(c0>>1)+cp]=*reinterpret_cast<u32*>(&ll);
        }
        __syncthreads();
    }
}
// ---- conv4 prep: w4 (Cin,Cout,3,3) -> per-tap MMA tiles hi/lo ----
__global__ void __launch_bounds__(256) prep_w4_kernel(const float* __restrict__ w4){
    const int idx=blockIdx.x*256+threadIdx.x;
    if(idx>=128*256*9)return;
    const int ci=idx/2304,r=idx%2304,co=r/9,k=r%9;
    float v=w4[idx];
    __nv_bfloat16 hi=__float2bfloat16(v);
    __nv_bfloat16 lo=__float2bfloat16(v-__bfloat162float(hi));
    const int dst=((k*4+(ci>>5))*256+co)*32+(ci&31);
    g_w4h[dst]=hi;g_w4l[dst]=lo;
}

// ---- conv4: HMMA implicit GEMM via subpixel decomposition, hi/lo 3-term ----
// Rounds: ee[0,4) tap w11; eo[4,12) w10,w12; oe[12,20) w01,w21; oo[20,36) w00,w02,w20,w22
static constexpr int C4_SMEM = 2*24576;
__global__ void __launch_bounds__(256) conv4_hmma_kernel(){
    extern __shared__ __align__(128) char dsm4[];
    const u32 sb=smem_u32(dsm4);
    const int tid=threadIdx.x,w=tid>>5,lane=tid&31;
    const int co0=blockIdx.x*128,Y=blockIdx.y,b=blockIdx.z;
    const int wm=w&3,wn=w>>2;
    const int i8=lane&7,q=lane>>3;
    const int g4=lane>>2,tg=lane&3;

    float acc[2][4][4];
#pragma unroll
    for(int mi=0;mi<2;++mi)
#pragma unroll
        for(int n8=0;n8<4;++n8)
#pragma unroll
            for(int j=0;j<4;++j)acc[mi][n8][j]=0.f;

    const int rA0=wm*32+i8+((q&1)<<3), rA1=rA0+16;
    const int cAq=(q>>1)<<4, cBq=(q&1)<<4;
    const int erow=tid>>2, ec=tid&3;

    auto stage=[&](int r,u32 sbase){
        int tap,dy,dx,ch;
        if(r<4){tap=4;dy=0;dx=0;ch=r;}
        else if(r<12){int t=(r-4)>>2;tap=t?5:3;dx=t^1;dy=0;ch=(r-4)&3;}
        else if(r<20){int t=(r-12)>>2;tap=t?7:1;dy=t^1;dx=0;ch=(r-12)&3;}
        else {int t=(r-20)>>2;tap=t*2+((t>>1)<<1);dy=(t<2)?1:0;dx=(t&1)^1;ch=(r-20)&3;}
        int ys=Y+dy, xs=erow+dx;
        u32 bsz=(ys<64&&xs<64)?16u:0u;
        if(ys>63)ys=63; if(xs>63)xs=63;
        const size_t bsrc=(((size_t)(b*64+ys)*64+xs)*128)+ch*32+ec*8;
        const u32 bo=toff(erow,ec*16);
        CPAZ(sbase+16384+bo,g_x3h+bsrc,bsz);
        CPAZ(sbase+20480+bo,g_x3l+bsrc,bsz);
        const size_t abase=((size_t)((tap*4+ch)*256+co0+erow))*32+ec*8;
        CPA(sbase+bo,g_w4h+abase);
        CPA(sbase+8192+bo,g_w4l+abase);
        const u32 bo2=toff(erow+64,ec*16);
        const size_t abase2=abase+(size_t)64*32;
        CPA(sbase+bo2,g_w4h+abase2);
        CPA(sbase+8192+bo2,g_w4l+abase2);
        CPA_COMMIT();
    };

    stage(0,sb);
    for(int r=0;r<36;++r){
        const u32 cur=sb+(u32)((r&1)*24576);
        if(r<35){
            stage(r+1,sb+(u32)(((r+1)&1)*24576));
            asm volatile("cp.async.wait_group 1;":::"memory");
        }else{
            asm volatile("cp.async.wait_group 0;":::"memory");
        }
        __syncthreads();
        const u32 uAh=cur,uAl=cur+8192,uBh=cur+16384,uBl=cur+20480;
#pragma unroll
        for(int ks=0;ks<2;++ks){
            const int k0b=ks*32;
            u32 Ah0[4],Ah1[4],Al0[4],Al1[4];
            LDSM4(Ah0,uAh+toff(rA0,k0b+cAq));
            LDSM4(Ah1,uAh+toff(rA1,k0b+cAq));
            LDSM4(Al0,uAl+toff(rA0,k0b+cAq));
            LDSM4(Al1,uAl+toff(rA1,k0b+cAq));
#pragma unroll
            for(int nb=0;nb<2;++nb){
                const int rB=wn*32+nb*16+i8+((q>>1)<<3);
                u32 Bh[4],Bl[4];
                LDSM4(Bh,uBh+toff(rB,k0b+cBq));
                LDSM4(Bl,uBl+toff(rB,k0b+cBq));
                MMA(acc[0][nb*2  ],Ah0,Bh[0],Bh[1]);
                MMA(acc[0][nb*2+1],Ah0,Bh[2],Bh[3]);
                MMA(acc[1][nb*2  ],Ah1,Bh[0],Bh[1]);
                MMA(acc[1][nb*2+1],Ah1,Bh[2],Bh[3]);
                MMA(acc[0][nb*2  ],Ah0,Bl[0],Bl[1]);
                MMA(acc[0][nb*2+1],Ah0,Bl[2],Bl[3]);
                MMA(acc[1][nb*2  ],Ah1,Bl[0],Bl[1]);
                MMA(acc[1][nb*2+1],Ah1,Bl[2],Bl[3]);
                MMA(acc[0][nb*2  ],Al0,Bh[0],Bh[1]);
                MMA(acc[0][nb*2+1],Al0,Bh[2],Bh[3]);
                MMA(acc[1][nb*2  ],Al1,Bh[0],Bh[1]);
                MMA(acc[1][nb*2+1],Al1,Bh[2],Bh[3]);
            }
        }
        __syncthreads();
        if(r==3||r==11||r==19||r==35){
            const int g=(r==3)?0:(r==11)?1:(r==19)?2:3;
            const int oy=g>>1,ox=g&1;
#pragma unroll
            for(int mi=0;mi<2;++mi){
                const int co=co0+wm*32+mi*16+g4;
                float* b0p=g_y4+((size_t)(b*256+co)*128+2*Y+oy)*128;
                float* b1p=b0p+(size_t)8*16384;
#pragma unroll
                for(int n8=0;n8<4;++n8){
                    const int x=wn*32+n8*8+tg*2;
                    b0p[2*x+ox]  =acc[mi][n8][0];
                    b0p[2*x+2+ox]=acc[mi][n8][1];
                    b1p[2*x+ox]  =acc[mi][n8][2];
                    b1p[2*x+2+ox]=acc[mi][n8][3];
                }
            }
#pragma unroll
            for(int mi=0;mi<2;++mi)
#pragma unroll
                for(int n8=0;n8<4;++n8)
#pragma unroll
                    for(int j=0;j<4;++j)acc[mi][n8][j]=0.f;
        }
    }
}

// ---- conv5 prep ----
__global__ void __launch_bounds__(256) prep_w_kernel(const float* __restrict__ w5){
    const int idx=blockIdx.x*256+threadIdx.x;
    if(idx>=512*2304)return;
    const int co=idx/2304,r=idx%2304,ci=r/9,k=r%9;
    float v=w5[idx];
    __nv_bfloat16 hi=__float2bfloat16(v);
    __nv_bfloat16 lo=__float2bfloat16(v-__bfloat162float(hi));
    const int dst=((k*8+(ci>>5))*512+co)*32+(ci&31);
    g_wh[dst]=hi;g_wl[dst]=lo;
}
__global__ void __launch_bounds__(256) prep_x_kernel(){
    __shared__ float tile[32][129];
    const int y=blockIdx.x,b=blockIdx.y,tid=threadIdx.x;
    u32* oh=reinterpret_cast<u32*>(g_xh)+((size_t)(b*128+y)*128)*128;
    u32* ol=reinterpret_cast<u32*>(g_xl)+((size_t)(b*128+y)*128)*128;
    for(int c0=0;c0<256;c0+=32){
        for(int e=tid;e<32*128;e+=256){
            const int cl=e>>7,x=e&127,ch=b*256+c0+cl;
            tile[cl][x]=nl(g_y4[((size_t)ch*128+y)*128+x],g_mean4[ch],g_inv4[ch]);
        }
        __syncthreads();
        for(int e=tid;e<128*16;e+=256){
            const int x=e>>4,cp=e&15;
            float v0=tile[2*cp][x],v1=tile[2*cp+1][x];
            __nv_bfloat16 h0=__float2bfloat16(v0),h1=__float2bfloat16(v1);
            __nv_bfloat16 l0=__float2bfloat16(v0-__bfloat162float(h0)),l1=__float2bfloat16(v1-__bfloat162float(h1));
            __nv_bfloat162 hh;hh.x=h0;hh.y=h1;
            __nv_bfloat162 ll;ll.x=l0;ll.y=l1;
            oh[(size_t)x*128+(c0>>1)+cp]=*reinterpret_cast<u32*>(&hh);
            ol[(size_t)x*128+(c0>>1)+cp]=*reinterpret_cast<u32*>(&ll);
        }
        __syncthreads();
    }
}

// ---- conv5: HMMA implicit GEMM + cp.async double-buffer + fused region pooling ----
static constexpr int C5_BINS = 65536;
static constexpr int C5_SLAB = C5_BINS + NS*128*4;
static constexpr int C5_SMEM = C5_SLAB + 512;
__global__ void __launch_bounds__(256) conv5_hmma_kernel(const float* __restrict__ bias){
    extern __shared__ __align__(128) char dsm[];
    const u32 sb=smem_u32(dsm);
    float* bins=reinterpret_cast<float*>(dsm+C5_BINS);
    int* slab=reinterpret_cast<int*>(dsm+C5_SLAB);
    const int tid=threadIdx.x,w=tid>>5,lane=tid&31;
    const int co0=blockIdx.x*128,y=blockIdx.y,b=blockIdx.z;
    const int wm=w&3,wn=w>>2;
    const int i8=lane&7,q=lane>>3;

    for(int i=tid;i<NS*128;i+=256)bins[i]=0.f;
    if(tid<128)slab[tid]=g_label[b*16384+y*128+tid];

    float acc[2][8][4];
#pragma unroll
    for(int mi=0;mi<2;++mi)
#pragma unroll
        for(int n8=0;n8<8;++n8)
#pragma unroll
            for(int j=0;j<4;++j)acc[mi][n8][j]=0.f;

    const int rA0=wm*32+i8+((q&1)<<3), rA1=rA0+16;
    const int rB0=wn*64+i8+((q>>1)<<3), rB1=rB0+16, rB2=rB0+32, rB3=rB0+48;
    const int cAq=(q>>1)<<4, cBq=(q&1)<<4;

    const int er=tid>>2, ec8=tid&3;
    const u32 sto=toff(er,ec8*16), sto2=toff(er+64,ec8*16);

    auto stage=[&](int r,u32 sbase){
        const int tap=r>>3,ch=r&7;
        const int ky=tap/3,kx=tap%3;
        int ys=y+ky-1; ys=ys<0?1:(ys>127?126:ys);
        int xs=er+kx-1; xs=xs<0?1:(xs>127?126:xs);
        const int er2=er+64;
        int xs2=er2+kx-1; xs2=xs2>127?126:xs2;
        const size_t a0=((size_t)(r*512+co0)+er)*32+ec8*8;
        const size_t a1=a0+(size_t)64*32;
        const size_t b0o=((size_t)(b*128+ys)*128+xs)*256+ch*32+ec8*8;
        const size_t b1o=((size_t)(b*128+ys)*128+xs2)*256+ch*32+ec8*8;
        const u32 d0=sbase+sto,d1=sbase+sto2;
        CPA(d0      ,g_wh+a0); CPA(d0+8192 ,g_wl+a0);
        CPA(d0+16384,g_xh+b0o);CPA(d0+24576,g_xl+b0o);
        CPA(d1      ,g_wh+a1); CPA(d1+8192 ,g_wl+a1);
        CPA(d1+16384,g_xh+b1o);CPA(d1+24576,g_xl+b1o);
        CPA_COMMIT();
    };

    stage(0,sb);
    for(int r=0;r<72;++r){
        const u32 cur=sb+(u32)((r&1)<<15);
        if(r<71){
            stage(r+1,sb+(u32)(((r+1)&1)<<15));
            asm volatile("cp.async.wait_group 1;":::"memory");
        }else{
            asm volatile("cp.async.wait_group 0;":::"memory");
        }
        __syncthreads();
        const u32 uAh=cur,uAl=cur+8192,uBh=cur+16384,uBl=cur+24576;
#pragma unroll
        for(int ks=0;ks<2;++ks){
            const int k0b=ks*32;
            u32 Ah0[4],Ah1[4],Al0[4],Al1[4];
            LDSM4(Ah0,uAh+toff(rA0,k0b+cAq));
            LDSM4(Ah1,uAh+toff(rA1,k0b+cAq));
            LDSM4(Al0,uAl+toff(rA0,k0b+cAq));
            LDSM4(Al1,uAl+toff(rA1,k0b+cAq));
            const int rB[4]={rB0,rB1,rB2,rB3};
#pragma unroll
            for(int nb=0;nb<4;++nb){
                u32 Bh[4],Bl[4];
                LDSM4(Bh,uBh+toff(rB[nb],k0b+cBq));
                LDSM4(Bl,uBl+toff(rB[nb],k0b+cBq));
                MMA(acc[0][nb*2  ],Ah0,Bh[0],Bh[1]);
                MMA(acc[0][nb*2+1],Ah0,Bh[2],Bh[3]);
                MMA(acc[1][nb*2  ],Ah1,Bh[0],Bh[1]);
                MMA(acc[1][nb*2+1],Ah1,Bh[2],Bh[3]);
                MMA(acc[0][nb*2  ],Ah0,Bl[0],Bl[1]);
                MMA(acc[0][nb*2+1],Ah0,Bl[2],Bl[3]);
                MMA(acc[1][nb*2  ],Ah1,Bl[0],Bl[1]);
                MMA(acc[1][nb*2+1],Ah1,Bl[2],Bl[3]);
                MMA(acc[0][nb*2  ],Al0,Bh[0],Bh[1]);
                MMA(acc[0][nb*2+1],Al0,Bh[2],Bh[3]);
                MMA(acc[1][nb*2  ],Al1,Bh[0],Bh[1]);
                MMA(acc[1][nb*2+1],Al1,Bh[2],Bh[3]);
            }
        }
        __syncthreads();
    }

    const int g4=lane>>2,tg=lane&3;
#pragma unroll
    for(int mi=0;mi<2;++mi){
        const int cr=wm*32+mi*16+g4;
        const float b0v=bias[co0+cr],b1v=bias[co0+cr+8];
#pragma unroll
        for(int n8=0;n8<8;++n8){
            const int x=wn*64+n8*8+tg*2;
            const int l0=slab[x],l1=slab[x+1];
            atomicAdd(&bins[l0*128+cr  ],tanh_fast(acc[mi][n8][0]+b0v));
            atomicAdd(&bins[l1*128+cr  ],tanh_fast(acc[mi][n8][1]+b0v));
            atomicAdd(&bins[l0*128+cr+8],tanh_fast(acc[mi][n8][2]+b1v));
            atomicAdd(&bins[l1*128+cr+8],tanh_fast(acc[mi][n8][3]+b1v));
        }
    }
    __syncthreads();
    for(int i=tid;i<NS*128;i+=256){
        const float v=bins[i];
        if(v!=0.f)atomicAdd(&g_sums[((size_t)b*NS+(i>>7))*512+co0+(i&127)],v);
    }
}

// ---- labels + counts ----
__global__ void __launch_bounds__(256) label_kernel(const float* __restrict__ segmap){
    const int b=blockIdx.x;
    __shared__ int cnt[NS];
    if(threadIdx.x<NS)cnt[threadIdx.x]=0;
    __syncthreads();
    for(int p=threadIdx.x;p<16384;p+=256){
        const int y=p>>7,x=p&127;
        const float* sp=segmap+(size_t)b*NS*65536+(size_t)(2*y)*256+2*x;
        int lab=0;
#pragma unroll
        for(int s=NS-1;s>=0;--s)
            if(sp[(size_t)s*65536]>0.f)lab=s;
        g_label[b*16384+p]=lab;
        atomicAdd(&cnt[lab],1);
    }
    __syncthreads();
    if(threadIdx.x<NS)g_counts[b*NS+threadIdx.x]=(float)cnt[threadIdx.x];
}
__global__ void __launch_bounds__(256) zero_sums_kernel(){
    const int i=blockIdx.x*256+threadIdx.x;
    if(i<NB*NS*512)g_sums[i]=0.f;
}
__global__ void __launch_bounds__(256) finalize_kernel(float* __restrict__ out){
    const int i=blockIdx.x*256+threadIdx.x;
    if(i>=NB*NS*512)return;
    const float cnt=g_counts[i>>9];
    out[i]=cnt>0.f?g_sums[i]/fmaxf(cnt,1.f):0.f;
}

extern "C" void kernel_launch(void* const* d_in, const int* in_sizes, int n_in,
                              void* d_out, int out_size)
{
    const float* input =(const float*)d_in[0];
    const float* segmap=(const float*)d_in[1];
    const float* w1=(const float*)d_in[2];
    const float* w2=(const float*)d_in[4];
    const float* w3=(const float*)d_in[6];
    const float* w4=(const float*)d_in[8];
    const float* w5=(const float*)d_in[10];
    const float* b5=(const float*)d_in[11];
    float* out=(float*)d_out;

    cudaFuncSetAttribute(conv5_hmma_kernel,cudaFuncAttributeMaxDynamicSharedMemorySize,C5_SMEM);
    cudaFuncSetAttribute(conv4_hmma_kernel,cudaFuncAttributeMaxDynamicSharedMemorySize,C4_SMEM);

    dim3 t2(16,16);
    prep_w_kernel<<<(512*2304+255)/256,256>>>(w5);
    zero_sums_kernel<<<(NB*NS*512+255)/256,256>>>();
    label_kernel<<<NB,256>>>(segmap);
    conv1_kernel<<<dim3(16,16,NB),t2>>>(input,w1);
    stats1_kernel<<<NB*32,256>>>();
    conv2_kernel<<<dim3(2,32,NB),t2>>>(w2);
    stats2_kernel<<<NB*64,256>>>();
    conv3_kernel<<<dim3(4,8,NB),t2>>>(w3);
    stats3_kernel<<<NB*128,256>>>();
    prep_w4_kernel<<<(128*256*9+255)/256,256>>>(w4);
    prep_x3_kernel<<<dim3(64,NB),256>>>();
    conv4_hmma_kernel<<<dim3(2,64,NB),256,C4_SMEM>>>();
    stats4_kernel<<<NB*256,256>>>();
    prep_x_kernel<<<dim3(128,NB),256>>>();
    conv5_hmma_kernel<<<dim3(4,128,NB),256,C5_SMEM>>>(b5);
    finalize_kernel<<<(NB*NS*512+255)/256,256>>>(out);
}

// round 13
// speedup vs baseline: 1.3982x; 1.1772x over previous
#include <cuda_runtime.h>
#include <cuda_bf16.h>
#include <cuda_fp16.h>
#include <math.h>

#define NB 8
#define NS 19
using u64 = unsigned long long;
using u32 = unsigned int;

__device__ float g_y1[(size_t)NB*32*256*256];
__device__ float g_y2[(size_t)NB*64*128*128];
__device__ float g_y3[(size_t)NB*128*64*64];
__device__ float g_y4[(size_t)NB*256*128*128];
__device__ float g_mean1[NB*32],  g_inv1[NB*32];
__device__ float g_mean2[NB*64],  g_inv2[NB*64];
__device__ float g_mean3[NB*128], g_inv3[NB*128];
__device__ float g_mean4[NB*256], g_inv4[NB*256];
__device__ int   g_label[NB*128*128];
__device__ float g_counts[NB*NS];
__device__ float g_sums[(size_t)NB*NS*512];
__device__ __half g_xh[(size_t)NB*128*128*256];         // conv5 input NHWC fp16 hi
__device__ __half g_xl[(size_t)NB*128*128*256];         // fp16 lo
__device__ __half g_w5f[9*8*512*32];                    // conv5 weights fp16 [tap*8+ch][co][ci32]
__device__ __nv_bfloat16 g_x3h[(size_t)NB*64*64*128];   // conv4 input NHWC hi (norm3+lrelu)
__device__ __nv_bfloat16 g_x3l[(size_t)NB*64*64*128];   // lo
__device__ __nv_bfloat16 g_w4h[9*4*256*32];             // conv4 weights [tap*4+ch][co][ci32] hi
__device__ __nv_bfloat16 g_w4l[9*4*256*32];             // lo

__device__ __forceinline__ u64 pk2(float v){u64 r;asm("mov.b64 %0,{%1,%1};":"=l"(r):"f"(v));return r;}
__device__ __forceinline__ u64 pk2(float a,float b){u64 r;asm("mov.b64 %0,{%1,%2};":"=l"(r):"f"(a),"f"(b));return r;}
__device__ __forceinline__ void fma2(u64&a,u64 v,u64 w){asm("fma.rn.f32x2 %0,%1,%2,%0;":"+l"(a):"l"(v),"l"(w));}
__device__ __forceinline__ float2 upk(u64 a){float2 f;asm("mov.b64 {%0,%1},%2;":"=f"(f.x),"=f"(f.y):"l"(a));return f;}
__device__ __forceinline__ float nl(float x,float m,float iv){float t=(x-m)*iv;return t>0.f?t:0.2f*t;}
__device__ __forceinline__ float tanh_fast(float x){float r;asm("tanh.approx.f32 %0,%1;":"=f"(r):"f"(x));return r;}
__device__ __forceinline__ u32 smem_u32(const void*p){u32 a;asm("{ .reg .u64 t; cvta.to.shared.u64 t,%1; cvt.u32.u64 %0,t; }":"=r"(a):"l"(p));return a;}

// row-pair packed swizzled tile offset: rows x 32 elems(2B) (64B rows, pairs share 128B)
__device__ __forceinline__ u32 toff(int row,int colb){
    u32 o=((u32)(row>>1)<<7)+((u32)(row&1)<<6)+(u32)colb;
    return o^((o>>3)&0x70);
}
#define LDSM4(r,addr) asm volatile("ldmatrix.sync.aligned.m8n8.x4.shared.b16 {%0,%1,%2,%3},[%4];" \
    :"=r"((r)[0]),"=r"((r)[1]),"=r"((r)[2]),"=r"((r)[3]):"r"(addr))
#define MMA(d,a,b0,b1) asm volatile("mma.sync.aligned.m16n8k16.row.col.f32.bf16.bf16.f32 " \
    "{%0,%1,%2,%3},{%4,%5,%6,%7},{%8,%9},{%0,%1,%2,%3};" \
    :"+f"((d)[0]),"+f"((d)[1]),"+f"((d)[2]),"+f"((d)[3]) \
    :"r"((a)[0]),"r"((a)[1]),"r"((a)[2]),"r"((a)[3]),"r"(b0),"r"(b1))
#define MMAH(d,a,b0,b1) asm volatile("mma.sync.aligned.m16n8k16.row.col.f32.f16.f16.f32 " \
    "{%0,%1,%2,%3},{%4,%5,%6,%7},{%8,%9},{%0,%1,%2,%3};" \
    :"+f"((d)[0]),"+f"((d)[1]),"+f"((d)[2]),"+f"((d)[3]) \
    :"r"((a)[0]),"r"((a)[1]),"r"((a)[2]),"r"((a)[3]),"r"(b0),"r"(b1))
#define CPA(dst,src) asm volatile("cp.async.ca.shared.global [%0],[%1],16;"::"r"(dst),"l"(src):"memory")
#define CPAZ(dst,src,ssz) asm volatile("cp.async.ca.shared.global [%0],[%1],16,%2;"::"r"(dst),"l"(src),"r"(ssz):"memory")
#define CPA_COMMIT() asm volatile("cp.async.commit_group;":::"memory")

// ---- conv1: 3->32, reflect, 256x256 ----
__global__ void __launch_bounds__(256) conv1_kernel(const float* __restrict__ x,const float* __restrict__ w){
    __shared__ float s_in[3][18][18];
    __shared__ u64 s_w[27][16];
    const int tx=threadIdx.x,ty=threadIdx.y,tid=ty*16+tx;
    const int ox0=blockIdx.x*16,oy0=blockIdx.y*16,b=blockIdx.z;
    for(int e=tid;e<27*16;e+=256){int j=e&15,r=e>>4;s_w[r][j]=pk2(w[(2*j)*27+r],w[(2*j+1)*27+r]);}
    for(int e=tid;e<3*18*18;e+=256){
        int c=e/324,r=e%324,yy=r/18,xx=r%18;
        int iy=oy0-1+yy;iy=iy<0?-iy:(iy>255?510-iy:iy);
        int ix=ox0-1+xx;ix=ix<0?-ix:(ix>255?510-ix:ix);
        s_in[c][yy][xx]=x[(((size_t)b*3+c)*256+iy)*256+ix];
    }
    __syncthreads();
    u64 acc[16];
#pragma unroll
    for(int j=0;j<16;++j)acc[j]=0ull;
#pragma unroll
    for(int c=0;c<3;++c)
#pragma unroll
        for(int k=0;k<9;++k){
            u64 vv=pk2(s_in[c][ty+k/3][tx+k%3]);
#pragma unroll
            for(int j=0;j<16;++j)fma2(acc[j],vv,s_w[c*9+k][j]);
        }
    float* yp=g_y1+(size_t)b*32*65536+(size_t)(oy0+ty)*256+ox0+tx;
#pragma unroll
    for(int j=0;j<16;++j){float2 v=upk(acc[j]);yp[(size_t)(2*j)*65536]=v.x;yp[(size_t)(2*j+1)*65536]=v.y;}
}

// ---- IN stats ----
__device__ __forceinline__ void stats_body(const float* __restrict__ y,float* mean,float* inv,int HW){
    const int ch=blockIdx.x;
    const float4* p=reinterpret_cast<const float4*>(y+(size_t)ch*HW);
    float s=0.f,ss=0.f;
    for(int i=threadIdx.x;i<(HW>>2);i+=256){float4 v=p[i];s+=v.x+v.y+v.z+v.w;ss+=v.x*v.x+v.y*v.y+v.z*v.z+v.w*v.w;}
#pragma unroll
    for(int o=16;o>0;o>>=1){s+=__shfl_xor_sync(~0u,s,o);ss+=__shfl_xor_sync(~0u,ss,o);}
    __shared__ float sh[2][8];
    const int wid=threadIdx.x>>5,lid=threadIdx.x&31;
    if(lid==0){sh[0][wid]=s;sh[1][wid]=ss;}
    __syncthreads();
    if(threadIdx.x==0){
        float ts=0.f,tss=0.f;
#pragma unroll
        for(int i=0;i<8;++i){ts+=sh[0][i];tss+=sh[1][i];}
        float m=ts/HW;mean[ch]=m;inv[ch]=rsqrtf(tss/HW-m*m+1e-5f);
    }
}
__global__ void __launch_bounds__(256) stats1_kernel(){stats_body(g_y1,g_mean1,g_inv1,65536);}
__global__ void __launch_bounds__(256) stats2_kernel(){stats_body(g_y2,g_mean2,g_inv2,16384);}
__global__ void __launch_bounds__(256) stats3_kernel(){stats_body(g_y3,g_mean3,g_inv3,4096);}
__global__ void __launch_bounds__(256) stats4_kernel(){stats_body(g_y4,g_mean4,g_inv4,16384);}

// ---- stride-2 conv ----
template<int CIN,int COUT,int HIN>
__device__ __forceinline__ void conv_s2_body(const float* __restrict__ x,const float* mean,const float* inv,
                                             const float* __restrict__ w,float* __restrict__ y){
    constexpr int HOUT=HIN/2,CK=4,TILESX=HOUT/32;
    __shared__ float s_in[CK][33][65];
    __shared__ u64 s_w[CK*9][16];
    const int tx=threadIdx.x,ty=threadIdx.y,tid=ty*16+tx;
    const int co0=blockIdx.x*32;
    const int oy0=(blockIdx.y/TILESX)*16,ox0=(blockIdx.y%TILESX)*32,b=blockIdx.z;
    u64 a0[16],a1[16];
#pragma unroll
    for(int j=0;j<16;++j){a0[j]=0ull;a1[j]=0ull;}
    for(int c0=0;c0<CIN;c0+=CK){
        __syncthreads();
        for(int e=tid;e<CK*9*16;e+=256){
            int j=e&15,r=e>>4,c=r/9,k=r%9;
            size_t base=((size_t)(co0+2*j)*CIN+c0+c)*9+k;
            s_w[r][j]=pk2(w[base],w[base+(size_t)CIN*9]);
        }
        for(int e=tid;e<CK*33*65;e+=256){
            int c=e/(33*65),r=e%(33*65),yy=r/65,xx=r%65;
            int iy=2*oy0-1+yy,ix=2*ox0-1+xx;float v=0.f;
            if(iy>=0&&iy<HIN&&ix>=0&&ix<HIN){int ch=b*CIN+c0+c;v=nl(x[((size_t)ch*HIN+iy)*HIN+ix],mean[ch],inv[ch]);}
            s_in[c][yy][xx]=v;
        }
        __syncthreads();
#pragma unroll
        for(int c=0;c<CK;++c)
#pragma unroll
            for(int k=0;k<9;++k){
                const int ky=k/3,kx=k%3;
                u64 v0=pk2(s_in[c][2*ty+ky][2*tx+kx]);
                u64 v1=pk2(s_in[c][2*ty+ky][2*(tx+16)+kx]);
#pragma unroll
                for(int j=0;j<16;++j){u64 wv=s_w[c*9+k][j];fma2(a0[j],v0,wv);fma2(a1[j],v1,wv);}
            }
    }
#pragma unroll
    for(int j=0;j<16;++j){
        float2 q0=upk(a0[j]),q1=upk(a1[j]);
        size_t base=((size_t)(b*COUT+co0+2*j)*HOUT+oy0+ty)*HOUT+ox0+tx;
        y[base]=q0.x;y[base+(size_t)HOUT*HOUT]=q0.y;y[base+16]=q1.x;y[base+(size_t)HOUT*HOUT+16]=q1.y;
    }
}
__global__ void __launch_bounds__(256) conv2_kernel(const float* __restrict__ w){conv_s2_body<32,64,256>(g_y1,g_mean1,g_inv1,w,g_y2);}
__global__ void __launch_bounds__(256) conv3_kernel(const float* __restrict__ w){conv_s2_body<64,128,128>(g_y2,g_mean2,g_inv2,w,g_y3);}

// ---- conv4 prep: y3 -> NHWC bf16 hi/lo (norm3+lrelu) ----
__global__ void __launch_bounds__(256) prep_x3_kernel(){
    __shared__ float t3[32][65];
    const int y=blockIdx.x,b=blockIdx.y,tid=threadIdx.x;
    u32* oh=reinterpret_cast<u32*>(g_x3h)+((size_t)(b*64+y)*64)*64;
    u32* ol=reinterpret_cast<u32*>(g_x3l)+((size_t)(b*64+y)*64)*64;
    for(int c0=0;c0<128;c0+=32){
        for(int e=tid;e<32*64;e+=256){
            const int cl=e>>6,x=e&63,ch=b*128+c0+cl;
            t3[cl][x]=nl(g_y3[((size_t)ch*64+y)*64+x],g_mean3[ch],g_inv3[ch]);
        }
        __syncthreads();
        for(int e=tid;e<64*16;e+=256){
            const int x=e>>4,cp=e&15;
            float v0=t3[2*cp][x],v1=t3[2*cp+1][x];
            __nv_bfloat16 h0=__float2bfloat16(v0),h1=__float2bfloat16(v1);
            __nv_bfloat16 l0=__float2bfloat16(v0-__bfloat162float(h0)),l1=__float2bfloat16(v1-__bfloat162float(h1));
            __nv_bfloat162 hh;hh.x=h0;hh.y=h1;
            __nv_bfloat162 ll;ll.x=l0;ll.y=l1;
            oh[(size_t)x*64+(c0>>1)+cp]=*reinterpret_cast<u32*>(&hh);
            ol[(size_t)x*64+(c0>>1)+cp]=*reinterpret_cast<u32*>(&ll);
        }
        __syncthreads();
    }
}
// ---- conv4 prep: w4 (Cin,Cout,3,3) -> per-tap MMA tiles hi/lo ----
__global__ void __launch_bounds__(256) prep_w4_kernel(const float* __restrict__ w4){
    const int idx=blockIdx.x*256+threadIdx.x;
    if(idx>=128*256*9)return;
    const int ci=idx/2304,r=idx%2304,co=r/9,k=r%9;
    float v=w4[idx];
    __nv_bfloat16 hi=__float2bfloat16(v);
    __nv_bfloat16 lo=__float2bfloat16(v-__bfloat162float(hi));
    const int dst=((k*4+(ci>>5))*256+co)*32+(ci&31);
    g_w4h[dst]=hi;g_w4l[dst]=lo;
}

// ---- conv4: HMMA implicit GEMM via subpixel decomposition, hi/lo 3-term ----
static constexpr int C4_SMEM = 2*24576;
__global__ void __launch_bounds__(256) conv4_hmma_kernel(){
    extern __shared__ __align__(128) char dsm4[];
    const u32 sb=smem_u32(dsm4);
    const int tid=threadIdx.x,w=tid>>5,lane=tid&31;
    const int co0=blockIdx.x*128,Y=blockIdx.y,b=blockIdx.z;
    const int wm=w&3,wn=w>>2;
    const int i8=lane&7,q=lane>>3;
    const int g4=lane>>2,tg=lane&3;

    float acc[2][4][4];
#pragma unroll
    for(int mi=0;mi<2;++mi)
#pragma unroll
        for(int n8=0;n8<4;++n8)
#pragma unroll
            for(int j=0;j<4;++j)acc[mi][n8][j]=0.f;

    const int rA0=wm*32+i8+((q&1)<<3), rA1=rA0+16;
    const int cAq=(q>>1)<<4, cBq=(q&1)<<4;
    const int erow=tid>>2, ec=tid&3;

    auto stage=[&](int r,u32 sbase){
        int tap,dy,dx,ch;
        if(r<4){tap=4;dy=0;dx=0;ch=r;}
        else if(r<12){int t=(r-4)>>2;tap=t?5:3;dx=t^1;dy=0;ch=(r-4)&3;}
        else if(r<20){int t=(r-12)>>2;tap=t?7:1;dy=t^1;dx=0;ch=(r-12)&3;}
        else {int t=(r-20)>>2;tap=t*2+((t>>1)<<1);dy=(t<2)?1:0;dx=(t&1)^1;ch=(r-20)&3;}
        int ys=Y+dy, xs=erow+dx;
        u32 bsz=(ys<64&&xs<64)?16u:0u;
        if(ys>63)ys=63; if(xs>63)xs=63;
        const size_t bsrc=(((size_t)(b*64+ys)*64+xs)*128)+ch*32+ec*8;
        const u32 bo=toff(erow,ec*16);
        CPAZ(sbase+16384+bo,g_x3h+bsrc,bsz);
        CPAZ(sbase+20480+bo,g_x3l+bsrc,bsz);
        const size_t abase=((size_t)((tap*4+ch)*256+co0+erow))*32+ec*8;
        CPA(sbase+bo,g_w4h+abase);
        CPA(sbase+8192+bo,g_w4l+abase);
        const u32 bo2=toff(erow+64,ec*16);
        const size_t abase2=abase+(size_t)64*32;
        CPA(sbase+bo2,g_w4h+abase2);
        CPA(sbase+8192+bo2,g_w4l+abase2);
        CPA_COMMIT();
    };

    stage(0,sb);
    for(int r=0;r<36;++r){
        const u32 cur=sb+(u32)((r&1)*24576);
        if(r<35){
            stage(r+1,sb+(u32)(((r+1)&1)*24576));
            asm volatile("cp.async.wait_group 1;":::"memory");
        }else{
            asm volatile("cp.async.wait_group 0;":::"memory");
        }
        __syncthreads();
        const u32 uAh=cur,uAl=cur+8192,uBh=cur+16384,uBl=cur+20480;
#pragma unroll
        for(int ks=0;ks<2;++ks){
            const int k0b=ks*32;
            u32 Ah0[4],Ah1[4],Al0[4],Al1[4];
            LDSM4(Ah0,uAh+toff(rA0,k0b+cAq));
            LDSM4(Ah1,uAh+toff(rA1,k0b+cAq));
            LDSM4(Al0,uAl+toff(rA0,k0b+cAq));
            LDSM4(Al1,uAl+toff(rA1,k0b+cAq));
#pragma unroll
            for(int nb=0;nb<2;++nb){
                const int rB=wn*32+nb*16+i8+((q>>1)<<3);
                u32 Bh[4],Bl[4];
                LDSM4(Bh,uBh+toff(rB,k0b+cBq));
                LDSM4(Bl,uBl+toff(rB,k0b+cBq));
                MMA(acc[0][nb*2  ],Ah0,Bh[0],Bh[1]);
                MMA(acc[0][nb*2+1],Ah0,Bh[2],Bh[3]);
                MMA(acc[1][nb*2  ],Ah1,Bh[0],Bh[1]);
                MMA(acc[1][nb*2+1],Ah1,Bh[2],Bh[3]);
                MMA(acc[0][nb*2  ],Ah0,Bl[0],Bl[1]);
                MMA(acc[0][nb*2+1],Ah0,Bl[2],Bl[3]);
                MMA(acc[1][nb*2  ],Ah1,Bl[0],Bl[1]);
                MMA(acc[1][nb*2+1],Ah1,Bl[2],Bl[3]);
                MMA(acc[0][nb*2  ],Al0,Bh[0],Bh[1]);
                MMA(acc[0][nb*2+1],Al0,Bh[2],Bh[3]);
                MMA(acc[1][nb*2  ],Al1,Bh[0],Bh[1]);
                MMA(acc[1][nb*2+1],Al1,Bh[2],Bh[3]);
            }
        }
        __syncthreads();
        if(r==3||r==11||r==19||r==35){
            const int g=(r==3)?0:(r==11)?1:(r==19)?2:3;
            const int oy=g>>1,ox=g&1;
#pragma unroll
            for(int mi=0;mi<2;++mi){
                const int co=co0+wm*32+mi*16+g4;
                float* b0p=g_y4+((size_t)(b*256+co)*128+2*Y+oy)*128;
                float* b1p=b0p+(size_t)8*16384;
#pragma unroll
                for(int n8=0;n8<4;++n8){
                    const int x=wn*32+n8*8+tg*2;
                    b0p[2*x+ox]  =acc[mi][n8][0];
                    b0p[2*x+2+ox]=acc[mi][n8][1];
                    b1p[2*x+ox]  =acc[mi][n8][2];
                    b1p[2*x+2+ox]=acc[mi][n8][3];
                }
            }
#pragma unroll
            for(int mi=0;mi<2;++mi)
#pragma unroll
                for(int n8=0;n8<4;++n8)
#pragma unroll
                    for(int j=0;j<4;++j)acc[mi][n8][j]=0.f;
        }
    }
}

// ---- conv5 prep: weights -> single fp16 tiles ----
__global__ void __launch_bounds__(256) prep_w_kernel(const float* __restrict__ w5){
    const int idx=blockIdx.x*256+threadIdx.x;
    if(idx>=512*2304)return;
    const int co=idx/2304,r=idx%2304,ci=r/9,k=r%9;
    const int dst=((k*8+(ci>>5))*512+co)*32+(ci&31);
    g_w5f[dst]=__float2half_rn(w5[idx]);
}
// ---- conv5 prep: y4 -> NHWC fp16 hi/lo (norm4+lrelu) ----
__global__ void __launch_bounds__(256) prep_x_kernel(){
    __shared__ float tile[32][129];
    const int y=blockIdx.x,b=blockIdx.y,tid=threadIdx.x;
    u32* oh=reinterpret_cast<u32*>(g_xh)+((size_t)(b*128+y)*128)*128;
    u32* ol=reinterpret_cast<u32*>(g_xl)+((size_t)(b*128+y)*128)*128;
    for(int c0=0;c0<256;c0+=32){
        for(int e=tid;e<32*128;e+=256){
            const int cl=e>>7,x=e&127,ch=b*256+c0+cl;
            tile[cl][x]=nl(g_y4[((size_t)ch*128+y)*128+x],g_mean4[ch],g_inv4[ch]);
        }
        __syncthreads();
        for(int e=tid;e<128*16;e+=256){
            const int x=e>>4,cp=e&15;
            float v0=tile[2*cp][x],v1=tile[2*cp+1][x];
            __half h0=__float2half_rn(v0),h1=__float2half_rn(v1);
            __half l0=__float2half_rn(v0-__half2float(h0)),l1=__float2half_rn(v1-__half2float(h1));
            __half2 hh;hh.x=h0;hh.y=h1;
            __half2 ll;ll.x=l0;ll.y=l1;
            oh[(size_t)x*128+(c0>>1)+cp]=*reinterpret_cast<u32*>(&hh);
            ol[(size_t)x*128+(c0>>1)+cp]=*reinterpret_cast<u32*>(&ll);
        }
        __syncthreads();
    }
}

// ---- conv5: fp16 2-term HMMA, N=256 (2 y-rows/CTA), cp.async pipeline, fused pooling ----
static constexpr int C5_BUF = 40960;                 // W 8K | B0H 8K | B0L 8K | B1H 8K | B1L 8K
static constexpr int C5_BINS = 2*C5_BUF;             // 81920
static constexpr int C5_SLAB = C5_BINS + NS*128*4;   // + 9728
static constexpr int C5_SMEM = C5_SLAB + 1024;
__global__ void __launch_bounds__(256) conv5_hmma_kernel(const float* __restrict__ bias){
    extern __shared__ __align__(128) char dsm[];
    const u32 sb=smem_u32(dsm);
    float* bins=reinterpret_cast<float*>(dsm+C5_BINS);
    int* slab=reinterpret_cast<int*>(dsm+C5_SLAB);
    const int tid=threadIdx.x,w=tid>>5,lane=tid&31;
    const int co0=blockIdx.x*128,y0=blockIdx.y*2,b=blockIdx.z;
    const int wm=w&3,wn=w>>2;
    const int i8=lane&7,q=lane>>3;

    for(int i=tid;i<NS*128;i+=256)bins[i]=0.f;
    slab[tid]=g_label[b*16384+(y0+(tid>>7))*128+(tid&127)];

    float acc[2][16][4];
#pragma unroll
    for(int mi=0;mi<2;++mi)
#pragma unroll
        for(int n8=0;n8<16;++n8)
#pragma unroll
            for(int j=0;j<4;++j)acc[mi][n8][j]=0.f;

    const int rA0=wm*32+i8+((q&1)<<3), rA1=rA0+16;
    const int rBb=wn*64+i8+((q>>1)<<3);
    const int cAq=(q>>1)<<4, cBq=(q&1)<<4;

    const int er=tid>>2, ec8=tid&3;
    const u32 sto=toff(er,ec8*16), sto2=toff(er+64,ec8*16);

    auto stage=[&](int r,u32 sbase){
        const int tap=r>>3,ch=r&7;
        const int ky=tap/3,kx=tap%3;
        int ys0=y0+ky-1;   ys0=ys0<0?1:(ys0>127?126:ys0);
        int ys1=y0+ky;     ys1=ys1>127?126:ys1;
        int xs=er+kx-1;    xs=xs<0?1:(xs>127?126:xs);
        int xs2=er+64+kx-1;xs2=xs2>127?126:xs2;
        const size_t a0=((size_t)(r*512+co0)+er)*32+ec8*8;
        const size_t a1=a0+(size_t)64*32;
        const size_t b00=((size_t)(b*128+ys0)*128+xs )*256+ch*32+ec8*8;
        const size_t b01=((size_t)(b*128+ys0)*128+xs2)*256+ch*32+ec8*8;
        const size_t b10=((size_t)(b*128+ys1)*128+xs )*256+ch*32+ec8*8;
        const size_t b11=((size_t)(b*128+ys1)*128+xs2)*256+ch*32+ec8*8;
        CPA(sbase+sto       ,g_w5f+a0); CPA(sbase+sto2       ,g_w5f+a1);
        CPA(sbase+8192+sto  ,g_xh+b00); CPA(sbase+8192+sto2  ,g_xh+b01);
        CPA(sbase+16384+sto ,g_xl+b00); CPA(sbase+16384+sto2 ,g_xl+b01);
        CPA(sbase+24576+sto ,g_xh+b10); CPA(sbase+24576+sto2 ,g_xh+b11);
        CPA(sbase+32768+sto ,g_xl+b10); CPA(sbase+32768+sto2 ,g_xl+b11);
        CPA_COMMIT();
    };

    stage(0,sb);
    for(int r=0;r<72;++r){
        const u32 cur=sb+(u32)((r&1)*C5_BUF);
        if(r<71){
            stage(r+1,sb+(u32)(((r+1)&1)*C5_BUF));
            asm volatile("cp.async.wait_group 1;":::"memory");
        }else{
            asm volatile("cp.async.wait_group 0;":::"memory");
        }
        __syncthreads();
        const u32 uW=cur;
#pragma unroll
        for(int ks=0;ks<2;++ks){
            const int k0b=ks*32;
            u32 A0[4],A1[4];
            LDSM4(A0,uW+toff(rA0,k0b+cAq));
            LDSM4(A1,uW+toff(rA1,k0b+cAq));
#pragma unroll
            for(int row=0;row<2;++row){
                const u32 uBh=cur+8192+(u32)row*16384,uBl=uBh+8192;
#pragma unroll
                for(int nb=0;nb<4;++nb){
                    const int rB=rBb+nb*16;
                    u32 Bh[4],Bl[4];
                    LDSM4(Bh,uBh+toff(rB,k0b+cBq));
                    LDSM4(Bl,uBl+toff(rB,k0b+cBq));
                    const int n8=row*8+nb*2;
                    MMAH(acc[0][n8  ],A0,Bh[0],Bh[1]);
                    MMAH(acc[0][n8+1],A0,Bh[2],Bh[3]);
                    MMAH(acc[1][n8  ],A1,Bh[0],Bh[1]);
                    MMAH(acc[1][n8+1],A1,Bh[2],Bh[3]);
                    MMAH(acc[0][n8  ],A0,Bl[0],Bl[1]);
                    MMAH(acc[0][n8+1],A0,Bl[2],Bl[3]);
                    MMAH(acc[1][n8  ],A1,Bl[0],Bl[1]);
                    MMAH(acc[1][n8+1],A1,Bl[2],Bl[3]);
                }
            }
        }
        __syncthreads();
    }

    const int g4=lane>>2,tg=lane&3;
#pragma unroll
    for(int mi=0;mi<2;++mi){
        const int cr=wm*32+mi*16+g4;
        const float b0v=bias[co0+cr],b1v=bias[co0+cr+8];
#pragma unroll
        for(int row=0;row<2;++row)
#pragma unroll
            for(int nb=0;nb<4;++nb){
#pragma unroll
                for(int hh=0;hh<2;++hh){
                    const int n8=row*8+nb*2+hh;
                    const int x=wn*64+(nb*2+hh)*8+tg*2;
                    const int l0=slab[row*128+x],l1=slab[row*128+x+1];
                    atomicAdd(&bins[l0*128+cr  ],tanh_fast(acc[mi][n8][0]+b0v));
                    atomicAdd(&bins[l1*128+cr  ],tanh_fast(acc[mi][n8][1]+b0v));
                    atomicAdd(&bins[l0*128+cr+8],tanh_fast(acc[mi][n8][2]+b1v));
                    atomicAdd(&bins[l1*128+cr+8],tanh_fast(acc[mi][n8][3]+b1v));
                }
            }
    }
    __syncthreads();
    for(int i=tid;i<NS*128;i+=256){
        const float v=bins[i];
        if(v!=0.f)atomicAdd(&g_sums[((size_t)b*NS+(i>>7))*512+co0+(i&127)],v);
    }
}

// ---- labels + counts ----
__global__ void __launch_bounds__(256) label_kernel(const float* __restrict__ segmap){
    const int b=blockIdx.x;
    __shared__ int cnt[NS];
    if(threadIdx.x<NS)cnt[threadIdx.x]=0;
    __syncthreads();
    for(int p=threadIdx.x;p<16384;p+=256){
        const int y=p>>7,x=p&127;
        const float* sp=segmap+(size_t)b*NS*65536+(size_t)(2*y)*256+2*x;
        int lab=0;
#pragma unroll
        for(int s=NS-1;s>=0;--s)
            if(sp[(size_t)s*65536]>0.f)lab=s;
        g_label[b*16384+p]=lab;
        atomicAdd(&cnt[lab],1);
    }
    __syncthreads();
    if(threadIdx.x<NS)g_counts[b*NS+threadIdx.x]=(float)cnt[threadIdx.x];
}
__global__ void __launch_bounds__(256) zero_sums_kernel(){
    const int i=blockIdx.x*256+threadIdx.x;
    if(i<NB*NS*512)g_sums[i]=0.f;
}
__global__ void __launch_bounds__(256) finalize_kernel(float* __restrict__ out){
    const int i=blockIdx.x*256+threadIdx.x;
    if(i>=NB*NS*512)return;
    const float cnt=g_counts[i>>9];
    out[i]=cnt>0.f?g_sums[i]/fmaxf(cnt,1.f):0.f;
}

extern "C" void kernel_launch(void* const* d_in, const int* in_sizes, int n_in,
                              void* d_out, int out_size)
{
    const float* input =(const float*)d_in[0];
    const float* segmap=(const float*)d_in[1];
    const float* w1=(const float*)d_in[2];
    const float* w2=(const float*)d_in[4];
    const float* w3=(const float*)d_in[6];
    const float* w4=(const float*)d_in[8];
    const float* w5=(const float*)d_in[10];
    const float* b5=(const float*)d_in[11];
    float* out=(float*)d_out;

    cudaFuncSetAttribute(conv5_hmma_kernel,cudaFuncAttributeMaxDynamicSharedMemorySize,C5_SMEM);
    cudaFuncSetAttribute(conv4_hmma_kernel,cudaFuncAttributeMaxDynamicSharedMemorySize,C4_SMEM);

    dim3 t2(16,16);
    prep_w_kernel<<<(512*2304+255)/256,256>>>(w5);
    zero_sums_kernel<<<(NB*NS*512+255)/256,256>>>();
    label_kernel<<<NB,256>>>(segmap);
    conv1_kernel<<<dim3(16,16,NB),t2>>>(input,w1);
    stats1_kernel<<<NB*32,256>>>();
    conv2_kernel<<<dim3(2,32,NB),t2>>>(w2);
    stats2_kernel<<<NB*64,256>>>();
    conv3_kernel<<<dim3(4,8,NB),t2>>>(w3);
    stats3_kernel<<<NB*128,256>>>();
    prep_w4_kernel<<<(128*256*9+255)/256,256>>>(w4);
    prep_x3_kernel<<<dim3(64,NB),256>>>();
    conv4_hmma_kernel<<<dim3(2,64,NB),256,C4_SMEM>>>();
    stats4_kernel<<<NB*256,256>>>();
    prep_x_kernel<<<dim3(128,NB),256>>>();
    conv5_hmma_kernel<<<dim3(4,64,NB),256,C5_SMEM>>>(b5);
    finalize_kernel<<<(NB*NS*512+255)/256,256>>>(out);
}